// round 14
// baseline (speedup 1.0000x reference)
#include <cuda_runtime.h>

// Chamfer distance, pc1/pc2: (1, 16384, 3) fp32 -> scalar fp32.
// R14: x-bin-sorted windowed BRUTE tiles (packed f32x2) + coverage verify +
//      warp-scan fallback. Exact & deterministic; threshold caps best at 2.0.

#define NP     16384
#define NB     4096
#define XMIN   (-6.0f)
#define XRANGE (12.0f)
#define BWID   (XRANGE / NB)
#define BW2    (2.0f * BWID)          // bin-granularity safety margin
#define INVBW  (NB / XRANGE)

#define QB     256                    // queries per phaseA block group
#define TB     128                    // phaseA threads (2 queries/thread, packed)
#define W      512                    // window margin (count) each side
#define SLICES 4
#define CH     256                    // smem chunk points

__device__ float4 s_pts[2][NP];       // x-bin-sorted; w = original index bits
__device__ int    bin_cnt[2][NB];     // zero at load; re-zeroed by reduce
__device__ int    bin_start[2][NB];
__device__ int    scatter_pos[2][NB];
__device__ int    g_d[2 * NP];        // float bits of NN d2 (<=2.0)
__device__ int4   fb_list[2 * NP];    // (dir, sorted q, wlo, whi)
__device__ int    fb_cnt;             // zero at load; re-zeroed by reduce

#define FMA2(out, a, b, c) \
    asm("fma.rn.f32x2 %0, %1, %2, %3;" : "=l"(out) : "l"(a), "l"(b), "l"(c))
#define ADD2(out, a, b) \
    asm("add.rn.f32x2 %0, %1, %2;" : "=l"(out) : "l"(a), "l"(b))
#define PACK2(out, lo, hi) \
    asm("mov.b64 %0, {%1, %2};" : "=l"(out) : "f"(lo), "f"(hi))
#define UNPACK2(lo, hi, in) \
    asm("mov.b64 {%0, %1}, %2;" : "=f"(lo), "=f"(hi) : "l"(in))
#define REDUX_MIN_S32(out, in) \
    asm("redux.sync.min.s32 %0, %1, 0xffffffff;" : "=r"(out) : "r"(in))

__device__ __forceinline__ int xbin(float x) {
    int b = (int)((x - XMIN) * INVBW);
    return min(max(b, 0), NB - 1);
}

__global__ void hist_kernel(const float* __restrict__ pc1,
                            const float* __restrict__ pc2) {
    int i = blockIdx.x * blockDim.x + threadIdx.x;     // 0..2NP-1
    int dir = i >> 14, idx = i & (NP - 1);
    const float* pc = dir ? pc2 : pc1;
    atomicAdd(&bin_cnt[dir][xbin(pc[3 * idx])], 1);
}

// One block, 1024 threads: exclusive prefix over 4096 bins, both dirs.
__global__ void __launch_bounds__(1024) scan_kernel() {
    __shared__ int wsum[32];
    int tid = threadIdx.x, lane = tid & 31, wid = tid >> 5;
#pragma unroll 1
    for (int dir = 0; dir < 2; dir++) {
        int base = tid * 4;
        int c0 = bin_cnt[dir][base + 0], c1 = bin_cnt[dir][base + 1];
        int c2 = bin_cnt[dir][base + 2], c3 = bin_cnt[dir][base + 3];
        int s0 = c0, s1 = s0 + c1, s2 = s1 + c2, s3 = s2 + c3;
        int tot = s3, v = tot;
#pragma unroll
        for (int o = 1; o < 32; o <<= 1) {
            int u = __shfl_up_sync(0xffffffffu, v, o);
            if (lane >= o) v += u;
        }
        if (lane == 31) wsum[wid] = v;
        __syncthreads();
        if (wid == 0) {
            int w = wsum[lane];
#pragma unroll
            for (int o = 1; o < 32; o <<= 1) {
                int u = __shfl_up_sync(0xffffffffu, w, o);
                if (lane >= o) w += u;
            }
            wsum[lane] = w;
        }
        __syncthreads();
        int warp_excl = (wid == 0) ? 0 : wsum[wid - 1];
        int ebase = warp_excl + (v - tot);
        bin_start[dir][base + 0] = ebase;
        bin_start[dir][base + 1] = ebase + s0;
        bin_start[dir][base + 2] = ebase + s1;
        bin_start[dir][base + 3] = ebase + s2;
        scatter_pos[dir][base + 0] = ebase;
        scatter_pos[dir][base + 1] = ebase + s0;
        scatter_pos[dir][base + 2] = ebase + s1;
        scatter_pos[dir][base + 3] = ebase + s2;
        __syncthreads();
    }
}

__global__ void scatter_kernel(const float* __restrict__ pc1,
                               const float* __restrict__ pc2) {
    int i = blockIdx.x * blockDim.x + threadIdx.x;
    int dir = i >> 14, idx = i & (NP - 1);
    const float* pc = dir ? pc2 : pc1;
    float x = pc[3 * idx], y = pc[3 * idx + 1], z = pc[3 * idx + 2];
    int pos = atomicAdd(&scatter_pos[dir][xbin(x)], 1);
    s_pts[dir][pos] = make_float4(x, y, z, __int_as_float(idx));
    g_d[i] = __float_as_int(2.0f);            // threshold cap = init
}

// Windowed brute tile: 256 consecutive sorted queries vs their shared
// candidate window (block min/max center +- W), sliced 4 ways across blocks.
__global__ void __launch_bounds__(TB) phaseA_kernel() {
    __shared__ float sh[CH * 8];
    __shared__ int wmn, wmx;
    const int tid   = threadIdx.x;
    const int qlo   = blockIdx.x * QB;
    const int slice = blockIdx.y;
    const int dir   = blockIdx.z;
    const float4* __restrict__ R = s_pts[dir ^ 1];

    if (tid == 0) { wmn = 0x7FFFFFFF; wmx = 0; }
    __syncthreads();

    const int qa = qlo + tid, qb = qlo + tid + TB;
    float4 pa = s_pts[dir][qa], pb = s_pts[dir][qb];
    int ca = bin_start[dir ^ 1][xbin(pa.x)];
    int cb = bin_start[dir ^ 1][xbin(pb.x)];
    atomicMin(&wmn, min(ca, cb));
    atomicMax(&wmx, max(ca, cb));
    __syncthreads();
    const int wlo = max(wmn - W, 0), whi = min(wmx + W, NP - 1);
    const int cnt = whi - wlo + 1;
    const int slo = wlo + (cnt * slice) / SLICES;
    const int shi = wlo + (cnt * (slice + 1)) / SLICES - 1;

    unsigned long long Qx, Qy, Qz, Qw;
    PACK2(Qx, pa.x, pb.x);
    PACK2(Qy, pa.y, pb.y);
    PACK2(Qz, pa.z, pb.z);
    PACK2(Qw, pa.x * pa.x + pa.y * pa.y + pa.z * pa.z,
              pb.x * pb.x + pb.y * pb.y + pb.z * pb.z);
    float ma = 2.0f, mb = 2.0f;

    for (int base = slo; base <= shi; base += CH) {
        int n = min(CH, shi - base + 1);
        __syncthreads();
        for (int i = tid; i < n; i += TB) {
            float4 r = R[base + i];
            float yy = r.x * r.x + r.y * r.y + r.z * r.z;
            float* s = &sh[i * 8];
            s[0] = -2.0f * r.x; s[1] = -2.0f * r.x;
            s[2] = -2.0f * r.y; s[3] = -2.0f * r.y;
            s[4] = -2.0f * r.z; s[5] = -2.0f * r.z;
            s[6] = yy;          s[7] = yy;
        }
        __syncthreads();
#pragma unroll 4
        for (int j = 0; j < n; j++) {
            const ulonglong2* sp = (const ulonglong2*)&sh[j * 8];
            ulonglong2 A = sp[0];
            ulonglong2 B = sp[1];
            unsigned long long u1, u2, d;
            FMA2(u1, Qx, A.x, B.y);     // yy - 2 x0 y0
            FMA2(u2, Qy, A.y, Qw);      // xx - 2 x1 y1
            FMA2(u1, Qz, B.x, u1);
            ADD2(d, u1, u2);            // full d2, packed (query a, query b)
            float lo, hi;
            UNPACK2(lo, hi, d);
            ma = fminf(ma, lo);
            mb = fminf(mb, hi);
        }
    }
    atomicMin(&g_d[dir * NP + __float_as_int(pa.w)], __float_as_int(ma));
    atomicMin(&g_d[dir * NP + __float_as_int(pb.w)], __float_as_int(mb));
}

// Coverage check per query (same window formula as phaseA); uncovered -> list.
__global__ void __launch_bounds__(QB) verify_kernel() {
    __shared__ int wmn, wmx;
    const int tid = threadIdx.x;
    const int qlo = blockIdx.x * QB;
    const int dir = blockIdx.y;
    if (tid == 0) { wmn = 0x7FFFFFFF; wmx = 0; }
    __syncthreads();
    const int q = qlo + tid;
    float4 p = s_pts[dir][q];
    int c = bin_start[dir ^ 1][xbin(p.x)];
    atomicMin(&wmn, c);
    atomicMax(&wmx, c);
    __syncthreads();
    const int wlo = max(wmn - W, 0), whi = min(wmx + W, NP - 1);
    const float4* __restrict__ R = s_pts[dir ^ 1];
    float best = __int_as_float(g_d[dir * NP + __float_as_int(p.w)]);
    float r = sqrtf(best) * 1.0001f;
    bool okL = (wlo == 0)      || (p.x - R[wlo].x - BW2 >= r);
    bool okR = (whi == NP - 1) || (R[whi].x - BW2 - p.x >= r);
    if (!(okL && okR)) {
        int k = atomicAdd(&fb_cnt, 1);
        fb_list[k] = make_int4(dir, q, wlo, whi);
    }
}

// Warp-per-query extension outward from window edges, best pre-seeded.
#define FTHR 256
__global__ void __launch_bounds__(FTHR) fallback_kernel() {
    const int lane = threadIdx.x & 31;
    const int gw   = blockIdx.x * (FTHR / 32) + (threadIdx.x >> 5);
    const int NW   = gridDim.x * (FTHR / 32);
    const int n    = fb_cnt;
    const bool leftside = lane < 16;
    const int lane16 = lane & 15;
    const int step = leftside ? -16 : 16;

    for (int t = gw; t < n; t += NW) {
        int4 e = fb_list[t];
        int dir = e.x, q = e.y;
        float4 p = s_pts[dir][q];
        const float4* __restrict__ R = s_pts[dir ^ 1];
        int gi = dir * NP + __float_as_int(p.w);
        float m = __int_as_float(g_d[gi]);
        float best = m;
        int j = leftside ? (e.z - 1 - lane16) : (e.w + 1 + lane16);
        bool sL = (e.z == 0), sR = (e.w == NP - 1);

        while (!(sL && sR)) {
            float dext = 1e30f;
            bool mydone = leftside ? sL : sR;
#pragma unroll
            for (int u = 0; u < 2; u++) {
                if (!mydone && j >= 0 && j < NP) {
                    float4 rr = R[j];
                    float dx = rr.x - p.x, dy = rr.y - p.y, dz = rr.z - p.z;
                    float d2 = fmaf(dx, dx, fmaf(dy, dy, dz * dz));
                    m = fminf(m, d2);
                    dext = leftside ? (p.x - rr.x) : (rr.x - p.x);
                } else {
                    dext = 1e30f;      // OOR/done: side exhausted
                }
                j += step;
            }
            int mbits; REDUX_MIN_S32(mbits, __float_as_int(m));
            best = __int_as_float(mbits);
            float eL = __shfl_sync(0xffffffffu, dext, 15);
            float eR = __shfl_sync(0xffffffffu, dext, 31);
            float bl = eL - BW2, br = eR - BW2;
            if (bl > 0.0f && bl * bl >= best) sL = true;
            if (br > 0.0f && br * br >= best) sR = true;
        }
        if (lane == 0) g_d[gi] = __float_as_int(best);
    }
}

// Fixed-order deterministic sum + threshold; re-zero bin_cnt/fb_cnt for the
// next graph replay (device globals persist across replays).
__global__ void __launch_bounds__(1024) reduce_kernel(float* __restrict__ out)
{
    const int tid = threadIdx.x;
    float s = 0.0f;
#pragma unroll
    for (int k = 0; k < (2 * NP) / 1024; k++) {
        float d = __int_as_float(g_d[tid + k * 1024]);
        if (d < 2.0f) s += d;                // untouched cap 2.0 -> 0
    }
#pragma unroll
    for (int k = 0; k < (2 * NB) / 1024; k++)
        ((int*)bin_cnt)[tid + k * 1024] = 0;
    if (tid == 0) fb_cnt = 0;

#pragma unroll
    for (int o = 16; o; o >>= 1) s += __shfl_xor_sync(0xFFFFFFFFu, s, o);

    __shared__ float ws[32];
    if ((tid & 31) == 0) ws[tid >> 5] = s;
    __syncthreads();
    if (tid < 32) {
        float v = ws[tid];
#pragma unroll
        for (int o = 16; o; o >>= 1) v += __shfl_xor_sync(0xFFFFFFFFu, v, o);
        if (tid == 0) out[0] = v * (1.0f / (float)NP);
    }
}

extern "C" void kernel_launch(void* const* d_in, const int* in_sizes, int n_in,
                              void* d_out, int out_size)
{
    const float* pc1 = (const float*)d_in[0];
    const float* pc2 = (const float*)d_in[1];
    float* out = (float*)d_out;

    hist_kernel<<<(2 * NP) / 1024, 1024>>>(pc1, pc2);
    scan_kernel<<<1, 1024>>>();
    scatter_kernel<<<(2 * NP) / 1024, 1024>>>(pc1, pc2);
    phaseA_kernel<<<dim3(NP / QB, SLICES, 2), TB>>>();   // 4th: ncu target
    verify_kernel<<<dim3(NP / QB, 2), QB>>>();
    fallback_kernel<<<64, FTHR>>>();
    reduce_kernel<<<1, 1024>>>(out);
}